// round 2
// baseline (speedup 1.0000x reference)
#include <cuda_runtime.h>

// out = outer(w, x) @ x0 + bias + x  ==  w * dot(x, x0) + bias + x
// D = 8192 floats = 2048 float4. Single-block fused kernel: 1024 threads,
// 2 float4 per thread. Dot reduction intra-CTA; no second launch, no global
// scratch round-trip.

#define NTHR 1024
#define V_PER_T 2   // 1024 * 2 = 2048 float4 = 8192 floats

__global__ void __launch_bounds__(NTHR) cross_fused_kernel(const float4* __restrict__ x0,
                                                           const float4* __restrict__ x,
                                                           const float4* __restrict__ w,
                                                           const float4* __restrict__ b,
                                                           float4* __restrict__ out) {
    const int t = threadIdx.x;
    const int i0 = t;
    const int i1 = t + NTHR;

    // Front-batch ALL loads: 8 independent LDG.128 -> single DRAM latency, full MLP.
    float4 a0 = x0[i0];
    float4 a1 = x0[i1];
    float4 xv0 = x[i0];
    float4 xv1 = x[i1];
    float4 wv0 = w[i0];
    float4 wv1 = w[i1];
    float4 bv0 = b[i0];
    float4 bv1 = b[i1];

    float s = a0.x * xv0.x + a0.y * xv0.y + a0.z * xv0.z + a0.w * xv0.w
            + a1.x * xv1.x + a1.y * xv1.y + a1.z * xv1.z + a1.w * xv1.w;

    // Warp reduction
    #pragma unroll
    for (int o = 16; o > 0; o >>= 1)
        s += __shfl_xor_sync(0xFFFFFFFFu, s, o);

    __shared__ float ws[NTHR / 32];   // 32 warp sums
    __shared__ float s_total;
    const int warp = t >> 5;
    const int lane = t & 31;
    if (lane == 0) ws[warp] = s;
    __syncthreads();

    if (warp == 0) {
        float v = ws[lane];   // 32 values, one per lane
        #pragma unroll
        for (int o = 16; o > 0; o >>= 1)
            v += __shfl_xor_sync(0xFFFFFFFFu, v, o);
        if (lane == 0) s_total = v;
    }
    __syncthreads();

    const float sv = s_total;

    float4 o0, o1;
    o0.x = fmaf(wv0.x, sv, bv0.x + xv0.x);
    o0.y = fmaf(wv0.y, sv, bv0.y + xv0.y);
    o0.z = fmaf(wv0.z, sv, bv0.z + xv0.z);
    o0.w = fmaf(wv0.w, sv, bv0.w + xv0.w);
    o1.x = fmaf(wv1.x, sv, bv1.x + xv1.x);
    o1.y = fmaf(wv1.y, sv, bv1.y + xv1.y);
    o1.z = fmaf(wv1.z, sv, bv1.z + xv1.z);
    o1.w = fmaf(wv1.w, sv, bv1.w + xv1.w);
    out[i0] = o0;
    out[i1] = o1;
}

extern "C" void kernel_launch(void* const* d_in, const int* in_sizes, int n_in,
                              void* d_out, int out_size) {
    const float4* x0 = (const float4*)d_in[0];
    const float4* x  = (const float4*)d_in[1];
    const float4* w  = (const float4*)d_in[2];
    const float4* b  = (const float4*)d_in[3];
    float4* out = (float4*)d_out;

    cross_fused_kernel<<<1, NTHR>>>(x0, x, w, b, out);
}

// round 5
// speedup vs baseline: 1.0337x; 1.0337x over previous
#include <cuda_runtime.h>

// out = outer(w, x) @ x0 + bias + x  ==  w * dot(x, x0) + bias + x
// D = 8192 floats = 2048 float4.
// Single launch, 8 CTAs x 256 threads. Each CTA redundantly computes the FULL
// dot(x, x0) (no inter-CTA dependency), then writes its 1/8 output slice.
// All loads front-batched for maximal MLP under one memory latency.

#define NCTAS 8
#define NTHR  256
#define V4_TOTAL 2048            // 8192 floats as float4
#define V4_PER_T (V4_TOTAL / NTHR)   // 8 float4 per tensor per thread for the dot
#define V4_PER_CTA (V4_TOTAL / NCTAS) // 256 float4 epilogue slice per CTA

__global__ void __launch_bounds__(NTHR) cross_fused_kernel(const float4* __restrict__ x0,
                                                           const float4* __restrict__ x,
                                                           const float4* __restrict__ w,
                                                           const float4* __restrict__ b,
                                                           float4* __restrict__ out) {
    const int t = threadIdx.x;

    // ---- Front-batch ALL loads (19 independent LDG.128) ----
    // Dot slices: strided so each warp's loads are coalesced.
    float4 a[V4_PER_T], xv[V4_PER_T];
    #pragma unroll
    for (int k = 0; k < V4_PER_T; k++) {
        a[k]  = x0[t + k * NTHR];
        xv[k] = x[t + k * NTHR];
    }
    // Epilogue slice loads (this CTA's 1/8 of the output).
    const int ei = blockIdx.x * V4_PER_CTA + t;
    float4 wv = w[ei];
    float4 bv = b[ei];
    float4 xe = x[ei];

    // ---- Partial dot ----
    float s = 0.f;
    #pragma unroll
    for (int k = 0; k < V4_PER_T; k++) {
        s += a[k].x * xv[k].x + a[k].y * xv[k].y
           + a[k].z * xv[k].z + a[k].w * xv[k].w;
    }

    // Warp reduction (5 shfl)
    #pragma unroll
    for (int o = 16; o > 0; o >>= 1)
        s += __shfl_xor_sync(0xFFFFFFFFu, s, o);

    __shared__ float ws[NTHR / 32];  // 8 warp sums
    __shared__ float s_total;
    const int warp = t >> 5;
    const int lane = t & 31;
    if (lane == 0) ws[warp] = s;
    __syncthreads();

    if (warp == 0) {
        float v = (lane < NTHR / 32) ? ws[lane] : 0.f;
        #pragma unroll
        for (int o = 4; o > 0; o >>= 1)
            v += __shfl_xor_sync(0xFFFFFFFFu, v, o);
        if (lane == 0) s_total = v;
    }
    __syncthreads();

    const float sv = s_total;

    // ---- Epilogue: out = w*s + (b + x) ----
    float4 o;
    o.x = fmaf(wv.x, sv, bv.x + xe.x);
    o.y = fmaf(wv.y, sv, bv.y + xe.y);
    o.z = fmaf(wv.z, sv, bv.z + xe.z);
    o.w = fmaf(wv.w, sv, bv.w + xe.w);
    out[ei] = o;
}

extern "C" void kernel_launch(void* const* d_in, const int* in_sizes, int n_in,
                              void* d_out, int out_size) {
    const float4* x0 = (const float4*)d_in[0];
    const float4* x  = (const float4*)d_in[1];
    const float4* w  = (const float4*)d_in[2];
    const float4* b  = (const float4*)d_in[3];
    float4* out = (float4*)d_out;

    cross_fused_kernel<<<NCTAS, NTHR>>>(x0, x, w, b, out);
}

// round 6
// speedup vs baseline: 1.0488x; 1.0146x over previous
#include <cuda_runtime.h>

// out = outer(w, x) @ x0 + bias + x  ==  w * dot(x, x0) + bias + x
// D = 8192 floats = 2048 float4.
// 8 CTAs x 256 threads, single launch. Each CTA redundantly computes the full
// dot; ONE barrier only: warp sums go to smem, then every thread broadcast-
// loads all 8 warp sums and adds them locally (shorter critical chain than a
// two-stage tree).

#define NCTAS 8
#define NTHR  256
#define NWARP (NTHR / 32)
#define V4_TOTAL 2048
#define V4_PER_T (V4_TOTAL / NTHR)    // 8
#define V4_PER_CTA (V4_TOTAL / NCTAS) // 256

__global__ void __launch_bounds__(NTHR) cross_fused_kernel(const float4* __restrict__ x0,
                                                           const float4* __restrict__ x,
                                                           const float4* __restrict__ w,
                                                           const float4* __restrict__ b,
                                                           float4* __restrict__ out) {
    const int t = threadIdx.x;

    // ---- Front-batch ALL loads (19 independent LDG.128) ----
    float4 a[V4_PER_T], xv[V4_PER_T];
    #pragma unroll
    for (int k = 0; k < V4_PER_T; k++) {
        a[k]  = x0[t + k * NTHR];
        xv[k] = x[t + k * NTHR];
    }
    const int ei = blockIdx.x * V4_PER_CTA + t;
    float4 wv = w[ei];
    float4 bv = b[ei];
    float4 xe = x[ei];

    // Epilogue additive part is independent of the reduction — fold early.
    float4 cv;
    cv.x = bv.x + xe.x;
    cv.y = bv.y + xe.y;
    cv.z = bv.z + xe.z;
    cv.w = bv.w + xe.w;

    // ---- Partial dot ----
    float s = 0.f;
    #pragma unroll
    for (int k = 0; k < V4_PER_T; k++) {
        s += a[k].x * xv[k].x + a[k].y * xv[k].y
           + a[k].z * xv[k].z + a[k].w * xv[k].w;
    }

    // Warp reduction (5 shfl)
    #pragma unroll
    for (int o = 16; o > 0; o >>= 1)
        s += __shfl_xor_sync(0xFFFFFFFFu, s, o);

    __shared__ float4 ws4[NWARP / 4];   // 8 warp sums as 2 float4 for LDS.128
    float* ws = (float*)ws4;
    const int warp = t >> 5;
    const int lane = t & 31;
    if (lane == 0) ws[warp] = s;
    __syncthreads();

    // Every thread: broadcast-load all 8 warp sums (2x LDS.128), sum locally.
    float4 u0 = ws4[0];
    float4 u1 = ws4[1];
    const float sv = ((u0.x + u0.y) + (u0.z + u0.w))
                   + ((u1.x + u1.y) + (u1.z + u1.w));

    // ---- Epilogue: out = w*s + (b + x) ----
    float4 o;
    o.x = fmaf(wv.x, sv, cv.x);
    o.y = fmaf(wv.y, sv, cv.y);
    o.z = fmaf(wv.z, sv, cv.z);
    o.w = fmaf(wv.w, sv, cv.w);
    out[ei] = o;
}

extern "C" void kernel_launch(void* const* d_in, const int* in_sizes, int n_in,
                              void* d_out, int out_size) {
    const float4* x0 = (const float4*)d_in[0];
    const float4* x  = (const float4*)d_in[1];
    const float4* w  = (const float4*)d_in[2];
    const float4* b  = (const float4*)d_in[3];
    float4* out = (float4*)d_out;

    cross_fused_kernel<<<NCTAS, NTHR>>>(x0, x, w, b, out);
}